// round 6
// baseline (speedup 1.0000x reference)
#include <cuda_runtime.h>
#include <cstdint>
#include <math.h>

#define T_STEPS 2048
#define BATCH   512
#define DIM     128
#define HID     128
#define NG      32          // 4 gates * 8 wires
#define TPB_TILES 8         // M-tiles (128 rows) per block
#define XS_FLOATS (128 * 132)
// smem: Xs0 | Xs1 | Ws(32*128) | bs(32) | sPC(128) | sPS(128)
#define GEMM_SMEM_FLOATS (2 * XS_FLOATS + 32 * 128 + 32 + 128 + 128)
#define GEMM_SMEM_BYTES  (GEMM_SMEM_FLOATS * 4)

__device__ float g_A[(size_t)T_STEPS * BATCH * NG];   // poly coeffs [row][gate][8]
__device__ float g_S[(size_t)(T_STEPS + 1) * BATCH];  // compact h chain + final c
__device__ float g_whsum[NG];
__device__ float g_PC[4][8][4];   // [jj][w][g] coeff of cos(z_w) in a_{2jj}
__device__ float g_PS[4][8][4];   // [jj][w][g] coeff of sin(z_w) in a_{2jj+1}

typedef unsigned long long u64;

__device__ __forceinline__ float tanh_fast(float x) {
    float r; asm("tanh.approx.f32 %0, %1;" : "=f"(r) : "f"(x)); return r;
}
__device__ __forceinline__ u64 ffma2(u64 a, u64 b, u64 c) {
    u64 d; asm("fma.rn.f32x2 %0, %1, %2, %3;" : "=l"(d) : "l"(a), "l"(b), "l"(c));
    return d;
}
__device__ __forceinline__ void cp16(uint32_t saddr, const void* gptr) {
    asm volatile("cp.async.cg.shared.global [%0], [%1], 16;" :: "r"(saddr), "l"(gptr));
}

// ---------------- init: whsum + Lagrange-on-Chebyshev coefficient tables ----------------
// q*sc interpolated as degree-7 poly in s on [-0.75, 0.75] (|h| <= sigmoid(1) = 0.731).
// q*sc = off - m*sum_w [cos(z_w)cos(whs_w s) - sin(z_w)sin(whs_w s)]; Chebyshev-node
// symmetry puts cos-terms in even monomials only, sin-terms in odd only.
__global__ void init_kernel(const float* __restrict__ Wf, const float* __restrict__ Wi,
                            const float* __restrict__ Wu, const float* __restrict__ Wo) {
    __shared__ double sL[8][8];
    const int n = threadIdx.x;         // 0..31
    const int g = n >> 3, w = n & 7;
    const float* W = (g == 0) ? Wf : (g == 1) ? Wi : (g == 2) ? Wu : Wo;
    float s = 0.f;
#pragma unroll
    for (int k = 0; k < 128; k++) s += W[w * 256 + 128 + k];
    g_whsum[n] = s;

    double xk[8];
#pragma unroll
    for (int k = 0; k < 8; k++) xk[k] = 0.75 * cos((2.0 * k + 1.0) * M_PI / 16.0);

    if (n < 8) {   // Lagrange basis L_n -> monomial coeffs (double)
        double cf[8];
        for (int i = 0; i < 8; i++) cf[i] = 0.0;
        cf[0] = 1.0;
        double den = 1.0;
        int deg = 0;
        for (int j = 0; j < 8; j++) {
            if (j == n) continue;
            for (int i = deg + 1; i >= 1; i--) cf[i] = cf[i - 1] - xk[j] * cf[i];
            cf[0] = -xk[j] * cf[0];
            deg++;
            den *= (xk[n] - xk[j]);
        }
        for (int j = 0; j < 8; j++) sL[n][j] = cf[j] / den;
    }
    __syncthreads();

    const double m = (g == 2) ? (1.0 / 16.0) : (1.0 / 32.0);
    for (int jj = 0; jj < 4; jj++) {
        double pc = 0.0, ps = 0.0;
        for (int k = 0; k < 8; k++) {
            double th = (double)s * xk[k];
            pc += sL[k][2 * jj]     * cos(th);
            ps += sL[k][2 * jj + 1] * sin(th);
        }
        g_PC[jj][w][g] = (float)(-m * pc);
        g_PS[jj][w][g] = (float)( m * ps);
    }
}

// ---------------- GEMM + fused eval, cp.async double-buffered ----------------
// 256 threads. Thread (wq = warp, lane): gate g = wq&3 (n = g*8..g*8+7),
// rows r0 = lane + 64*(wq>>2) and r0+32. Each thread owns a full (row,gate)
// Z-octet in registers -> eval fused with no Z staging.
__global__ void __launch_bounds__(256) gemm_kernel(
    const float* __restrict__ X,
    const float* __restrict__ Wf, const float* __restrict__ bf,
    const float* __restrict__ Wi, const float* __restrict__ bi,
    const float* __restrict__ Wu, const float* __restrict__ bu,
    const float* __restrict__ Wo, const float* __restrict__ bo) {
    extern __shared__ float sm[];
    float* Xb[2] = {sm, sm + XS_FLOATS};
    float* Ws  = sm + 2 * XS_FLOATS;       // [32][128]
    float* bs  = Ws + 32 * 128;            // [32]
    float* sPC = bs + 32;                  // [4][8][4]
    float* sPS = sPC + 128;                // [4][8][4]
    const int tid = threadIdx.x;
    const uint32_t sb0 = (uint32_t)__cvta_generic_to_shared(Xb[0]);
    const uint32_t sb1 = (uint32_t)__cvta_generic_to_shared(Xb[1]);

    const size_t tile0 = (size_t)blockIdx.x * TPB_TILES;
    // async load of one 128x128 tile: 4096 float4, 16 per thread
    auto issue = [&](uint32_t sb, size_t tile) {
        const float* src = X + tile * 128 * 128;
#pragma unroll
        for (int i = 0; i < 16; i++) {
            int idx = tid + i * 256;
            int m = idx >> 5, j = idx & 31;
            cp16(sb + (m * 132 + j * 4) * 4, src + m * 128 + j * 4);
        }
        asm volatile("cp.async.commit_group;" ::: "memory");
    };
    issue(sb0, tile0);   // overlap tile-0 load with smem staging below

    if (tid < 128)      sPC[tid] = ((const float*)g_PC)[tid];
    else                sPS[tid - 128] = ((const float*)g_PS)[tid - 128];
#pragma unroll
    for (int i = 0; i < 16; i++) {
        int idx = tid + i * 256;
        int n = idx >> 7, k = idx & 127;
        int gg = n >> 3, w = n & 7;
        const float* W = (gg == 0) ? Wf : (gg == 1) ? Wi : (gg == 2) ? Wu : Wo;
        Ws[n * 128 + k] = W[w * 256 + k];
    }
    if (tid < 32) {
        int gg = tid >> 3, w = tid & 7;
        const float* bb = (gg == 0) ? bf : (gg == 1) ? bi : (gg == 2) ? bu : bo;
        bs[tid] = bb[w];
    }
    __syncthreads();   // bs/Ws/sPC/sPS staged before ANY thread reads them (R5 bug fix)

    const int lane = tid & 31;
    const int wq = tid >> 5;
    const int g  = wq & 3;
    const int r0 = lane + 64 * (wq >> 2);
    const float off = (g == 2) ? 0.5f : 0.25f;
    float bias[8];
#pragma unroll
    for (int w = 0; w < 8; w++) bias[w] = bs[g * 8 + w];

    for (int it = 0; it < TPB_TILES; it++) {
        if (it + 1 < TPB_TILES) {
            issue((it & 1) ? sb0 : sb1, tile0 + it + 1);
            asm volatile("cp.async.wait_group 1;" ::: "memory");
        } else {
            asm volatile("cp.async.wait_group 0;" ::: "memory");
        }
        __syncthreads();

        const float* xb = Xb[it & 1];
        u64 acc[2][8];
#pragma unroll
        for (int j = 0; j < 2; j++)
#pragma unroll
            for (int n = 0; n < 8; n++) acc[j][n] = 0ull;

#pragma unroll 4
        for (int k = 0; k < 128; k += 4) {
            ulonglong2 A0 = *(const ulonglong2*)(xb + r0 * 132 + k);
            ulonglong2 A1 = *(const ulonglong2*)(xb + (r0 + 32) * 132 + k);
            ulonglong2 Bv[8];
#pragma unroll
            for (int n = 0; n < 8; n++)
                Bv[n] = *(const ulonglong2*)(Ws + (g * 8 + n) * 128 + k);
#pragma unroll
            for (int n = 0; n < 8; n++) {
                acc[0][n] = ffma2(A0.x, Bv[n].x, acc[0][n]);
                acc[0][n] = ffma2(A0.y, Bv[n].y, acc[0][n]);
                acc[1][n] = ffma2(A1.x, Bv[n].x, acc[1][n]);
                acc[1][n] = ffma2(A1.y, Bv[n].y, acc[1][n]);
            }
        }
        __syncthreads();   // mainloop LDS reads of xb done; reuse xb as As staging

        float* As = (float*)xb;   // pitch 36
#pragma unroll
        for (int j = 0; j < 2; j++) {
            const int r = r0 + 32 * j;
            float ae[4] = {off, 0.f, 0.f, 0.f}, ao[4] = {0.f, 0.f, 0.f, 0.f};
#pragma unroll
            for (int w = 0; w < 8; w++) {
                float2 p = *(float2*)&acc[j][w];
                float z = (p.x + p.y) + bias[w];
                float ca = __cosf(z), sa = __sinf(z);
#pragma unroll
                for (int jj = 0; jj < 4; jj++) {
                    ae[jj] = fmaf(ca, sPC[(jj * 8 + w) * 4 + g], ae[jj]);
                    ao[jj] = fmaf(sa, sPS[(jj * 8 + w) * 4 + g], ao[jj]);
                }
            }
            float4* dst = (float4*)(As + r * 36 + g * 8);
            dst[0] = make_float4(ae[0], ao[0], ae[1], ao[1]);
            dst[1] = make_float4(ae[2], ao[2], ae[3], ao[3]);
        }
        __syncthreads();
        // coalesced store As -> g_A (1024 float4)
        const size_t mrow0 = (tile0 + it) * 128;
#pragma unroll
        for (int i = 0; i < 4; i++) {
            int idx = tid + i * 256;
            int m = idx >> 3, q = idx & 7;
            float4 v = *(const float4*)(As + m * 36 + q * 4);
            *(float4*)(g_A + (mrow0 + m) * 32 + q * 4) = v;
        }
        __syncthreads();   // As reads done before next prefetch overwrites it
    }
}

// ---------------- rnn: one warp per chain; compact scalar output only ----------------
__global__ void __launch_bounds__(32) rnn_kernel() {
    const int b = blockIdx.x;
    const int l = threadIdx.x;
    const int g = l & 3;               // lanes mirror lanes 0-3 (uniform lines)
    const float vm = (g == 2) ? 1.0f : 0.5f;
    const float va = (g == 2) ? 0.0f : 0.5f;

    const float* ap = g_A + (size_t)b * NG + g * 8;
    const size_t ASTR = (size_t)BATCH * NG;

    float4 p0[16], p1[16];
#pragma unroll
    for (int q = 0; q < 16; q++) {
        p0[q] = *(const float4*)(ap + (size_t)q * ASTR);
        p1[q] = *(const float4*)(ap + (size_t)q * ASTR + 4);
    }
    float s = 0.f, c = 0.f;
    for (int t0 = 0; t0 < T_STEPS; t0 += 16) {
#pragma unroll
        for (int q = 0; q < 16; q++) {
            float4 A0 = p0[q], A1 = p1[q];
            int tn = t0 + 16 + q;
            if (tn < T_STEPS) {
                p0[q] = *(const float4*)(ap + (size_t)tn * ASTR);
                p1[q] = *(const float4*)(ap + (size_t)tn * ASTR + 4);
            }
            // Estrin degree-7: coeffs a0..a7 = (A0.x..A0.w, A1.x..A1.w)
            float s2 = s * s, s4 = s2 * s2;
            float b0 = fmaf(A0.y, s, A0.x);
            float b1 = fmaf(A0.w, s, A0.z);
            float b2 = fmaf(A1.y, s, A1.x);
            float b3 = fmaf(A1.w, s, A1.z);
            float c0 = fmaf(b1, s2, b0);
            float c1 = fmaf(b3, s2, b2);
            float qv = fmaf(c1, s4, c0);
            float val = fmaf(vm, tanh_fast(qv), va);
            float f = __shfl_sync(0xffffffffu, val, 0);
            float i = __shfl_sync(0xffffffffu, val, 1);
            float u = __shfl_sync(0xffffffffu, val, 2);
            float o = __shfl_sync(0xffffffffu, val, 3);
            c = fmaf(f, c, i * u);
            s = o * tanh_fast(c);
            if (l == 0) g_S[(size_t)(t0 + q) * BATCH + b] = s;
        }
    }
    if (l == 0) g_S[(size_t)T_STEPS * BATCH + b] = c;
}

// ---------------- expand: broadcast g_S scalars into the [.,.,128] output ----------------
__global__ void __launch_bounds__(256) expand_kernel(float4* __restrict__ out) {
    const size_t idx = (size_t)blockIdx.x * 256 + threadIdx.x;
    const size_t row = idx >> 5;
    const int b  = (int)(row & (BATCH - 1));
    const int tt = (int)(row >> 9);
    size_t src = row;
    if (tt == T_STEPS)     src = (size_t)(T_STEPS - 1) * BATCH + b;  // hx
    else if (tt > T_STEPS) src = (size_t)T_STEPS * BATCH + b;        // cx
    const float s = __ldg(&g_S[src]);
    const float4 v = make_float4(s, s, s, s);
    __stcs(&out[idx], v);
}

extern "C" void kernel_launch(void* const* d_in, const int* in_sizes, int n_in,
                              void* d_out, int out_size) {
    const float* X  = (const float*)d_in[0];
    const float* Wf = (const float*)d_in[1];
    const float* bf = (const float*)d_in[2];
    const float* Wi = (const float*)d_in[3];
    const float* bi = (const float*)d_in[4];
    const float* Wu = (const float*)d_in[5];
    const float* bu = (const float*)d_in[6];
    const float* Wo = (const float*)d_in[7];
    const float* bo = (const float*)d_in[8];
    float* out = (float*)d_out;

    cudaFuncSetAttribute(gemm_kernel, cudaFuncAttributeMaxDynamicSharedMemorySize,
                         GEMM_SMEM_BYTES);

    init_kernel<<<1, 32>>>(Wf, Wi, Wu, Wo);
    gemm_kernel<<<(T_STEPS * BATCH / 128) / TPB_TILES, 256, GEMM_SMEM_BYTES>>>(
        X, Wf, bf, Wi, bi, Wu, bu, Wo, bo);
    rnn_kernel<<<BATCH, 32>>>();
    expand_kernel<<<((T_STEPS + 2) * BATCH * 32) / 256, 256>>>((float4*)out);
}